// round 16
// baseline (speedup 1.0000x reference)
#include <cuda_runtime.h>
#include <cstdint>

// ---------------------------------------------------------------------------
// Problem constants
// ---------------------------------------------------------------------------
#define DIM   1024
#define SEQ   1024
#define BATCH 4
#define NH    16
#define HDIM  64
#define FFD   4096
#define NL    6
#define MROWS (BATCH * SEQ)   // 4096
#define VOCAB 32000

// ---------------------------------------------------------------------------
// Scratch (static device globals -- no allocation allowed)
// ---------------------------------------------------------------------------
__device__ float g_x [MROWS * DIM];
__device__ float g_y [MROWS * DIM];
__device__ float g_q [MROWS * DIM];
__device__ float g_k [MROWS * DIM];
__device__ float g_v [MROWS * DIM];
__device__ float g_t [MROWS * DIM];
__device__ float g_ff[MROWS * FFD];

// bf16 hi/lo planes (pre-converted operands)
__device__ uint16_t g_wh [(size_t)VOCAB * DIM];
__device__ uint16_t g_wl [(size_t)VOCAB * DIM];
__device__ uint16_t g_aqh[(size_t)MROWS * DIM];
__device__ uint16_t g_aql[(size_t)MROWS * DIM];
__device__ uint16_t g_akh[(size_t)MROWS * DIM];
__device__ uint16_t g_akl[(size_t)MROWS * DIM];
__device__ uint16_t g_avh[(size_t)MROWS * DIM];   // V transposed per head: [b*DIM+d][seq]
__device__ uint16_t g_avl[(size_t)MROWS * DIM];
__device__ uint16_t g_ffh[(size_t)MROWS * FFD];
__device__ uint16_t g_ffl[(size_t)MROWS * FFD];

// ---------------------------------------------------------------------------
// bf16 split helpers. packbf: e0 in LOW 16 bits (memory-first order).
// ---------------------------------------------------------------------------
__device__ __forceinline__ uint32_t packbf(float e0, float e1) {
    uint32_t r;
    asm("cvt.rn.bf16x2.f32 %0, %1, %2;" : "=r"(r) : "f"(e1), "f"(e0));
    return r;
}
__device__ __forceinline__ float bf_lo(uint32_t p) { return __uint_as_float(p << 16); }
__device__ __forceinline__ float bf_hi(uint32_t p) { return __uint_as_float(p & 0xFFFF0000u); }

__device__ __forceinline__ uint32_t smem_u32(const void* p) {
    uint32_t a;
    asm("{ .reg .u64 t; cvta.to.shared.u64 t, %1; cvt.u32.u64 %0, t; }"
        : "=r"(a) : "l"(p));
    return a;
}

// m16n8k16 row.col bf16 MMA, fp32 accumulate (arch-agnostic, sm_80+)
__device__ __forceinline__ void mma_bf16(float* d, const uint32_t* a, const uint32_t* b) {
    asm volatile(
        "mma.sync.aligned.m16n8k16.row.col.f32.bf16.bf16.f32 "
        "{%0,%1,%2,%3}, {%4,%5,%6,%7}, {%8,%9}, {%0,%1,%2,%3};\n"
        : "+f"(d[0]), "+f"(d[1]), "+f"(d[2]), "+f"(d[3])
        : "r"(a[0]), "r"(a[1]), "r"(a[2]), "r"(a[3]), "r"(b[0]), "r"(b[1]));
}

#define CP_ASYNC16(d, s) \
    asm volatile("cp.async.cg.shared.global [%0], [%1], 16;\n" :: "r"(d), "l"(s))
#define CP_COMMIT() asm volatile("cp.async.commit_group;\n" ::: "memory")
#define CP_WAIT_1() asm volatile("cp.async.wait_group 1;\n" ::: "memory")
#define CP_WAIT_0() asm volatile("cp.async.wait_group 0;\n" ::: "memory")

// ---------------------------------------------------------------------------
// conv_a: elementwise fp32 -> bf16 hi/lo planes (same layout)
// ---------------------------------------------------------------------------
__global__ __launch_bounds__(256)
void conv_a_kernel(const float* __restrict__ A, uint16_t* __restrict__ Ah,
                   uint16_t* __restrict__ Al)
{
    size_t i = (size_t)blockIdx.x * 256 + threadIdx.x;
    float4 a = ((const float4*)A)[i];
    uint32_t h01 = packbf(a.x, a.y);
    uint32_t h23 = packbf(a.z, a.w);
    uint32_t l01 = packbf(a.x - bf_lo(h01), a.y - bf_hi(h01));
    uint32_t l23 = packbf(a.z - bf_lo(h23), a.w - bf_hi(h23));
    ((uint2*)Ah)[i] = make_uint2(h01, h23);
    ((uint2*)Al)[i] = make_uint2(l01, l23);
}

// ---------------------------------------------------------------------------
// conv_w: W[K][N] fp32 -> Wt[N][K] bf16 hi/lo (transpose-convert, 32x32 tiles)
// ---------------------------------------------------------------------------
__global__ __launch_bounds__(256)
void conv_w_kernel(const float* __restrict__ B, uint16_t* __restrict__ Bth,
                   uint16_t* __restrict__ Btl, int K, int N)
{
    __shared__ float t[32][33];
    const int k0 = blockIdx.y << 5, n0 = blockIdx.x << 5;
    const int tid = threadIdx.x;
    const int r = tid >> 5, c = tid & 31;
#pragma unroll
    for (int i = 0; i < 4; i++)
        t[r + i * 8][c] = B[(size_t)(k0 + r + i * 8) * N + n0 + c];
    __syncthreads();
#pragma unroll
    for (int it = 0; it < 2; it++) {
        int idx = tid + it * 256;
        int n = idx >> 4, kp = (idx & 15) << 1;
        float b0 = t[kp][n], b1 = t[kp + 1][n];
        uint32_t h = packbf(b0, b1);
        uint32_t l = packbf(b0 - bf_lo(h), b1 - bf_hi(h));
        *(uint32_t*)&Bth[(size_t)(n0 + n) * K + k0 + kp] = h;
        *(uint32_t*)&Btl[(size_t)(n0 + n) * K + k0 + kp] = l;
    }
}

// ---------------------------------------------------------------------------
// conv_vt: V fp32 [b*SEQ+s][DIM] -> Vt bf16 hi/lo [(b*DIM+d)][SEQ]
// grid = (SEQ/32, DIM/32, BATCH)
// ---------------------------------------------------------------------------
__global__ __launch_bounds__(256)
void conv_vt_kernel(const float* __restrict__ V, uint16_t* __restrict__ Vth,
                    uint16_t* __restrict__ Vtl)
{
    __shared__ float tbuf[32][33];
    const int b = blockIdx.z;
    const int s0 = blockIdx.x << 5, d0 = blockIdx.y << 5;
    const int tid = threadIdx.x;
    const int r = tid >> 5, c = tid & 31;
#pragma unroll
    for (int i = 0; i < 4; i++)
        tbuf[r + i * 8][c] = V[(size_t)(b * SEQ + s0 + r + i * 8) * DIM + d0 + c];
    __syncthreads();
#pragma unroll
    for (int it = 0; it < 2; it++) {
        int idx = tid + it * 256;
        int n = idx >> 4, sp = (idx & 15) << 1;
        float v0 = tbuf[sp][n], v1 = tbuf[sp + 1][n];
        uint32_t hh = packbf(v0, v1);
        uint32_t ll = packbf(v0 - bf_lo(hh), v1 - bf_hi(hh));
        size_t o = (size_t)(b * DIM + d0 + n) * SEQ + s0 + sp;
        *(uint32_t*)&Vth[o] = hh;
        *(uint32_t*)&Vtl[o] = ll;
    }
}

// ---------------------------------------------------------------------------
// Tensor-core GEMM on pre-packed bf16 hi/lo planes.
// K chunks of 32, 2-stage double buffer, 80 KB smem -> 2 CTAs/SM.
// 128x128 CTA tile, 8 warps (2m x 4n), warp tile 64x32 (4x4 m16n8k16).
// LDAW=40 bf16 per row: fragment word idx = g*20+t covers 32 banks ->
// conflict-free LDS.32.
// ---------------------------------------------------------------------------
#define LDAW 40
#define PLANE_B (128 * LDAW * 2)          // 10240 bytes per plane
#define STAGE_B (4 * PLANE_B)             // 40960 bytes per stage
#define TG_SMEM_BYTES (2 * STAGE_B)       // 81920

__global__ __launch_bounds__(256, 2)
void tgemm_pk(const uint16_t* __restrict__ Ah, const uint16_t* __restrict__ Al,
              const uint16_t* __restrict__ Bth, const uint16_t* __restrict__ Btl,
              const float* __restrict__ bias, float* __restrict__ C,
              int M, int N, int K, int relu)
{
    extern __shared__ __align__(16) char smem[];
    const int tid  = threadIdx.x;
    const int wid  = tid >> 5;
    const int lane = tid & 31;
    const int wm   = wid & 1;
    const int wn   = wid >> 1;
    const int brow = blockIdx.y << 7;
    const int bcol = blockIdx.x << 7;
    const uint32_t sb = smem_u32(smem);

    const char* gp[4];
    gp[0] = (const char*)(Ah  + (size_t)brow * K);
    gp[1] = (const char*)(Al  + (size_t)brow * K);
    gp[2] = (const char*)(Bth + (size_t)bcol * K);
    gp[3] = (const char*)(Btl + (size_t)bcol * K);

    const int row_c = tid >> 2;          // copy row (0..63 per pass)
    const int ch_c  = tid & 3;           // 16B chunk within 64B row

    float acc[4][4][4];
#pragma unroll
    for (int mt = 0; mt < 4; mt++)
#pragma unroll
        for (int nt = 0; nt < 4; nt++)
#pragma unroll
            for (int i = 0; i < 4; i++) acc[mt][nt][i] = 0.f;

    const int NCH = K >> 5;

    // ---- prefetch chunk 0 into stage 0 ----
    {
#pragma unroll
        for (int p = 0; p < 4; p++) {
            uint32_t sp = sb + p * PLANE_B;
            const char* g = gp[p];
#pragma unroll
            for (int it = 0; it < 2; it++) {
                int row = row_c + it * 64;
                CP_ASYNC16(sp + row * 80 + ch_c * 16,
                           g + (size_t)row * K * 2 + ch_c * 16);
            }
        }
        CP_COMMIT();
    }

    for (int c = 0; c < NCH; c++) {
        if (c + 1 < NCH) {
            const size_t koff = (size_t)(c + 1) * 64;   // 32 elems * 2B
            uint32_t s0 = sb + ((c + 1) & 1) * STAGE_B;
#pragma unroll
            for (int p = 0; p < 4; p++) {
                uint32_t sp = s0 + p * PLANE_B;
                const char* g = gp[p] + koff;
#pragma unroll
                for (int it = 0; it < 2; it++) {
                    int row = row_c + it * 64;
                    CP_ASYNC16(sp + row * 80 + ch_c * 16,
                               g + (size_t)row * K * 2 + ch_c * 16);
                }
            }
            CP_COMMIT();
            CP_WAIT_1();
        } else {
            CP_WAIT_0();
        }
        __syncthreads();

        const uint16_t* Ahs = (const uint16_t*)(smem + (c & 1) * STAGE_B);
        const uint16_t* Als = Ahs + 128 * LDAW;
        const uint16_t* Bhs = Als + 128 * LDAW;
        const uint16_t* Bls = Bhs + 128 * LDAW;

        const int ar = wm * 64 + (lane >> 2);
        const int bc = wn * 32 + (lane >> 2);
        const int kf = (lane & 3) << 1;
#pragma unroll
        for (int ks = 0; ks < 2; ks++) {
            const int k0 = ks * 16 + kf;

            uint32_t af[4][4];
#pragma unroll
            for (int mt = 0; mt < 4; mt++) {
                int base = (ar + mt * 16) * LDAW + k0;
                af[mt][0] = *(const uint32_t*)&Ahs[base];
                af[mt][1] = *(const uint32_t*)&Ahs[base + 8 * LDAW];
                af[mt][2] = *(const uint32_t*)&Ahs[base + 8];
                af[mt][3] = *(const uint32_t*)&Ahs[base + 8 * LDAW + 8];
            }
            uint32_t bfh[4][2];
#pragma unroll
            for (int nt = 0; nt < 4; nt++) {
                int base = (bc + nt * 8) * LDAW + k0;
                bfh[nt][0] = *(const uint32_t*)&Bhs[base];
                bfh[nt][1] = *(const uint32_t*)&Bhs[base + 8];
            }
            // hi * hi
#pragma unroll
            for (int mt = 0; mt < 4; mt++)
#pragma unroll
                for (int nt = 0; nt < 4; nt++)
                    mma_bf16(acc[mt][nt], af[mt], bfh[nt]);

            // hi * lo
            uint32_t bfl[4][2];
#pragma unroll
            for (int nt = 0; nt < 4; nt++) {
                int base = (bc + nt * 8) * LDAW + k0;
                bfl[nt][0] = *(const uint32_t*)&Bls[base];
                bfl[nt][1] = *(const uint32_t*)&Bls[base + 8];
            }
#pragma unroll
            for (int mt = 0; mt < 4; mt++)
#pragma unroll
                for (int nt = 0; nt < 4; nt++)
                    mma_bf16(acc[mt][nt], af[mt], bfl[nt]);

            // lo * hi (reuse af registers)
#pragma unroll
            for (int mt = 0; mt < 4; mt++) {
                int base = (ar + mt * 16) * LDAW + k0;
                af[mt][0] = *(const uint32_t*)&Als[base];
                af[mt][1] = *(const uint32_t*)&Als[base + 8 * LDAW];
                af[mt][2] = *(const uint32_t*)&Als[base + 8];
                af[mt][3] = *(const uint32_t*)&Als[base + 8 * LDAW + 8];
            }
#pragma unroll
            for (int mt = 0; mt < 4; mt++)
#pragma unroll
                for (int nt = 0; nt < 4; nt++)
                    mma_bf16(acc[mt][nt], af[mt], bfh[nt]);
        }
        __syncthreads();
    }

    // ---- epilogue: bias (+ReLU), direct global stores ----
    const int rb = brow + wm * 64 + (lane >> 2);
    const int cb = bcol + wn * 32 + ((lane & 3) << 1);
#pragma unroll
    for (int nt = 0; nt < 4; nt++) {
        int col = cb + nt * 8;
        float2 bb = *(const float2*)&bias[col];
#pragma unroll
        for (int mt = 0; mt < 4; mt++) {
            int row = rb + mt * 16;
            float2 r0, r1;
            r0.x = acc[mt][nt][0] + bb.x;
            r0.y = acc[mt][nt][1] + bb.y;
            r1.x = acc[mt][nt][2] + bb.x;
            r1.y = acc[mt][nt][3] + bb.y;
            if (relu) {
                r0.x = fmaxf(r0.x, 0.f); r0.y = fmaxf(r0.y, 0.f);
                r1.x = fmaxf(r1.x, 0.f); r1.y = fmaxf(r1.y, 0.f);
            }
            *(float2*)&C[(size_t)row * N + col]       = r0;
            *(float2*)&C[(size_t)(row + 8) * N + col] = r1;
        }
    }
}

// ---------------------------------------------------------------------------
// Fused flash attention (bf16 split-3 MMA, online softmax). Unchanged (R15).
// ---------------------------------------------------------------------------
#define FL_QB    18432
#define FL_KB    18432
#define FL_VB    17408
#define FL_STG   (2 * FL_KB + 2 * FL_VB)
#define FL_SMEM  (2 * FL_QB + 2 * FL_STG + 256)

__global__ __launch_bounds__(256)
void flash_kernel(const uint16_t* __restrict__ Qh, const uint16_t* __restrict__ Ql,
                  const uint16_t* __restrict__ Kh, const uint16_t* __restrict__ Kl,
                  const uint16_t* __restrict__ Vth, const uint16_t* __restrict__ Vtl,
                  const int* __restrict__ tok, float* __restrict__ Og, int causal)
{
    extern __shared__ __align__(16) char sm[];
    const int tid = threadIdx.x, wid = tid >> 5, lane = tid & 31;
    const int g = lane >> 2, t = lane & 3;
    const int bh = blockIdx.y, b = bh >> 4, h = bh & 15;
    const int q0 = blockIdx.x << 7;
    const uint32_t sb = smem_u32(sm);

    const uint16_t* sqh = (const uint16_t*)sm;
    const uint16_t* sql = sqh + 9216;
    char* kok = sm + 2 * FL_QB + 2 * FL_STG;

    const char* Qh_b = (const char*)(Qh + (size_t)(b * SEQ + q0) * DIM + h * HDIM);
    const char* Ql_b = (const char*)(Ql + (size_t)(b * SEQ + q0) * DIM + h * HDIM);
    const char* Kh_b = (const char*)(Kh + (size_t)(b * SEQ) * DIM + h * HDIM);
    const char* Kl_b = (const char*)(Kl + (size_t)(b * SEQ) * DIM + h * HDIM);
    const char* Vh_b = (const char*)(Vth + ((size_t)b * DIM + h * HDIM) * SEQ);
    const char* Vl_b = (const char*)(Vtl + ((size_t)b * DIM + h * HDIM) * SEQ);

    {
        int row = tid >> 3, ch = tid & 7;
#pragma unroll
        for (int it = 0; it < 4; it++) {
            int r = row + it * 32;
            CP_ASYNC16(sb + r * 144 + ch * 16, Qh_b + (size_t)r * (DIM * 2) + ch * 16);
            CP_ASYNC16(sb + FL_QB + r * 144 + ch * 16, Ql_b + (size_t)r * (DIM * 2) + ch * 16);
        }
    }

    auto issue_kv = [&](int kt) {
        int s = kt & 1;
        uint32_t st = sb + 2 * FL_QB + s * FL_STG;
        int row = tid >> 3, ch = tid & 7;
#pragma unroll
        for (int it = 0; it < 4; it++) {
            int r = row + it * 32;
            size_t go = (size_t)(kt * 128 + r) * (DIM * 2) + ch * 16;
            CP_ASYNC16(st + r * 144 + ch * 16, Kh_b + go);
            CP_ASYNC16(st + FL_KB + r * 144 + ch * 16, Kl_b + go);
        }
        int vrow = tid >> 4, vch = tid & 15;
#pragma unroll
        for (int it = 0; it < 4; it++) {
            int d = vrow + it * 16;
            size_t go = (size_t)d * (SEQ * 2) + (size_t)kt * 256 + vch * 16;
            CP_ASYNC16(st + 2 * FL_KB + d * 272 + vch * 16, Vh_b + go);
            CP_ASYNC16(st + 2 * FL_KB + FL_VB + d * 272 + vch * 16, Vl_b + go);
        }
        if (!causal && tid < 128)
            kok[s * 128 + tid] = (char)(tok[b * SEQ + kt * 128 + tid] != 0);
    };
    issue_kv(0);
    CP_COMMIT();

    const int qrow0 = q0 + wid * 16 + g;
    const int qrow1 = qrow0 + 8;
    int qok0 = 1, qok1 = 1;
    if (causal) {
        qok0 = tok[b * SEQ + qrow0] != 0;
        qok1 = tok[b * SEQ + qrow1] != 0;
    }

    float m0 = -1e30f, m1 = -1e30f, l0 = 0.f, l1 = 0.f;
    float Oa[8][4];
#pragma unroll
    for (int i = 0; i < 8; i++) { Oa[i][0] = Oa[i][1] = Oa[i][2] = Oa[i][3] = 0.f; }

    const int NKT = SEQ / 128;
    const int arow = wid * 16 + g;

    for (int kt = 0; kt < NKT; kt++) {
        if (kt + 1 < NKT) { issue_kv(kt + 1); CP_COMMIT(); CP_WAIT_1(); }
        else               { CP_WAIT_0(); }
        __syncthreads();

        const uint16_t* skh = (const uint16_t*)(sm + 2 * FL_QB + (kt & 1) * FL_STG);
        const uint16_t* skl = skh + 9216;
        const uint16_t* svh = (const uint16_t*)((const char*)skh + 2 * FL_KB);
        const uint16_t* svl = svh + 8704;
        const char* kokc = kok + (kt & 1) * 128;

        float acc[16][4];
#pragma unroll
        for (int nt = 0; nt < 16; nt++)
            acc[nt][0] = acc[nt][1] = acc[nt][2] = acc[nt][3] = 0.f;

#pragma unroll 1
        for (int ks = 0; ks < 4; ks++) {
            const int ab = arow * 72 + ks * 16 + t * 2;
            uint32_t aH[4], aL[4];
            aH[0] = *(const uint32_t*)&sqh[ab];
            aH[1] = *(const uint32_t*)&sqh[ab + 8 * 72];
            aH[2] = *(const uint32_t*)&sqh[ab + 8];
            aH[3] = *(const uint32_t*)&sqh[ab + 8 * 72 + 8];
            aL[0] = *(const uint32_t*)&sql[ab];
            aL[1] = *(const uint32_t*)&sql[ab + 8 * 72];
            aL[2] = *(const uint32_t*)&sql[ab + 8];
            aL[3] = *(const uint32_t*)&sql[ab + 8 * 72 + 8];
#pragma unroll
            for (int nt = 0; nt < 16; nt++) {
                const int bb = (nt * 8 + g) * 72 + ks * 16 + t * 2;
                uint32_t bH[2], bL[2];
                bH[0] = *(const uint32_t*)&skh[bb];
                bH[1] = *(const uint32_t*)&skh[bb + 8];
                bL[0] = *(const uint32_t*)&skl[bb];
                bL[1] = *(const uint32_t*)&skl[bb + 8];
                mma_bf16(acc[nt], aH, bH);
                mma_bf16(acc[nt], aH, bL);
                mma_bf16(acc[nt], aL, bH);
            }
        }

        const int kbase = kt * 128;
#pragma unroll
        for (int nt = 0; nt < 16; nt++) {
            int j0 = nt * 8 + t * 2, j1 = j0 + 1;
            int v00, v01, v10, v11;
            if (causal) {
                int kc0 = kbase + j0, kc1 = kbase + j1;
                v00 = qok0 && (kc0 <= qrow0); v01 = qok0 && (kc1 <= qrow0);
                v10 = qok1 && (kc0 <= qrow1); v11 = qok1 && (kc1 <= qrow1);
            } else {
                int kv0 = kokc[j0], kv1 = kokc[j1];
                v00 = kv0; v01 = kv1; v10 = kv0; v11 = kv1;
            }
            acc[nt][0] = v00 ? acc[nt][0] * 0.125f : -1e9f;
            acc[nt][1] = v01 ? acc[nt][1] * 0.125f : -1e9f;
            acc[nt][2] = v10 ? acc[nt][2] * 0.125f : -1e9f;
            acc[nt][3] = v11 ? acc[nt][3] * 0.125f : -1e9f;
        }

        float mx0 = -1e30f, mx1 = -1e30f;
#pragma unroll
        for (int nt = 0; nt < 16; nt++) {
            mx0 = fmaxf(mx0, fmaxf(acc[nt][0], acc[nt][1]));
            mx1 = fmaxf(mx1, fmaxf(acc[nt][2], acc[nt][3]));
        }
        mx0 = fmaxf(mx0, __shfl_xor_sync(0xffffffffu, mx0, 1));
        mx0 = fmaxf(mx0, __shfl_xor_sync(0xffffffffu, mx0, 2));
        mx1 = fmaxf(mx1, __shfl_xor_sync(0xffffffffu, mx1, 1));
        mx1 = fmaxf(mx1, __shfl_xor_sync(0xffffffffu, mx1, 2));

        float m0n = fmaxf(m0, mx0), m1n = fmaxf(m1, mx1);
        float sc0 = __expf(m0 - m0n), sc1 = __expf(m1 - m1n);
        float s0 = 0.f, s1 = 0.f;
#pragma unroll
        for (int nt = 0; nt < 16; nt++) {
            float p0 = __expf(acc[nt][0] - m0n);
            float p1 = __expf(acc[nt][1] - m0n);
            float p2 = __expf(acc[nt][2] - m1n);
            float p3 = __expf(acc[nt][3] - m1n);
            acc[nt][0] = p0; acc[nt][1] = p1; acc[nt][2] = p2; acc[nt][3] = p3;
            s0 += p0 + p1; s1 += p2 + p3;
        }
        s0 += __shfl_xor_sync(0xffffffffu, s0, 1);
        s0 += __shfl_xor_sync(0xffffffffu, s0, 2);
        s1 += __shfl_xor_sync(0xffffffffu, s1, 1);
        s1 += __shfl_xor_sync(0xffffffffu, s1, 2);
        l0 = l0 * sc0 + s0;
        l1 = l1 * sc1 + s1;
        m0 = m0n; m1 = m1n;
#pragma unroll
        for (int ntd = 0; ntd < 8; ntd++) {
            Oa[ntd][0] *= sc0; Oa[ntd][1] *= sc0;
            Oa[ntd][2] *= sc1; Oa[ntd][3] *= sc1;
        }

#pragma unroll
        for (int ks2 = 0; ks2 < 8; ks2++) {
            uint32_t pH[4], pL[4];
            pH[0] = packbf(acc[2 * ks2][0],     acc[2 * ks2][1]);
            pH[1] = packbf(acc[2 * ks2][2],     acc[2 * ks2][3]);
            pH[2] = packbf(acc[2 * ks2 + 1][0], acc[2 * ks2 + 1][1]);
            pH[3] = packbf(acc[2 * ks2 + 1][2], acc[2 * ks2 + 1][3]);
            pL[0] = packbf(acc[2 * ks2][0] - bf_lo(pH[0]),     acc[2 * ks2][1] - bf_hi(pH[0]));
            pL[1] = packbf(acc[2 * ks2][2] - bf_lo(pH[1]),     acc[2 * ks2][3] - bf_hi(pH[1]));
            pL[2] = packbf(acc[2 * ks2 + 1][0] - bf_lo(pH[2]), acc[2 * ks2 + 1][1] - bf_hi(pH[2]));
            pL[3] = packbf(acc[2 * ks2 + 1][2] - bf_lo(pH[3]), acc[2 * ks2 + 1][3] - bf_hi(pH[3]));
#pragma unroll
            for (int ntd = 0; ntd < 8; ntd++) {
                int vb = (ntd * 8 + g) * 136 + ks2 * 16 + t * 2;
                uint32_t vH[2], vL[2];
                vH[0] = *(const uint32_t*)&svh[vb];
                vH[1] = *(const uint32_t*)&svh[vb + 8];
                vL[0] = *(const uint32_t*)&svl[vb];
                vL[1] = *(const uint32_t*)&svl[vb + 8];
                mma_bf16(Oa[ntd], pH, vH);
                mma_bf16(Oa[ntd], pH, vL);
                mma_bf16(Oa[ntd], pL, vH);
            }
        }
    }

    float i0 = 1.f / l0, i1 = 1.f / l1;
    float* o0 = Og + (size_t)(b * SEQ + qrow0) * DIM + h * HDIM;
    float* o1 = Og + (size_t)(b * SEQ + qrow1) * DIM + h * HDIM;
#pragma unroll
    for (int ntd = 0; ntd < 8; ntd++) {
        int dc = ntd * 8 + t * 2;
        *(float2*)&o0[dc] = make_float2(Oa[ntd][0] * i0, Oa[ntd][1] * i0);
        *(float2*)&o1[dc] = make_float2(Oa[ntd][2] * i1, Oa[ntd][3] * i1);
    }
}

// ---------------------------------------------------------------------------
// Embedding + sinusoidal positional encoding
// ---------------------------------------------------------------------------
__global__ __launch_bounds__(256)
void embed_kernel(const int* __restrict__ tok, const float* __restrict__ emb,
                  float* __restrict__ out)
{
    int bs = blockIdx.x;
    int s  = bs & (SEQ - 1);
    int t  = tok[bs];
    const float* e = emb + (size_t)t * DIM;
    float* o = out + (size_t)bs * DIM;
    const float c = (float)(-9.210340371976184 / 1024.0);
#pragma unroll
    for (int i = 0; i < 4; i++) {
        int d  = threadIdx.x + i * 256;
        int i2 = d & ~1;
        float div = expf((float)i2 * c);
        float ang = (float)s * div;
        float pe  = (d & 1) ? cosf(ang) : sinf(ang);
        o[d] = e[d] + pe;
    }
}

// ---------------------------------------------------------------------------
// x = LayerNorm(x + a) * g + b  (in place on x)
// ---------------------------------------------------------------------------
__global__ __launch_bounds__(256)
void add_ln_kernel(float* __restrict__ x, const float* __restrict__ a,
                   const float* __restrict__ g, const float* __restrict__ b)
{
    __shared__ float red[9];
    size_t base = (size_t)blockIdx.x * DIM;
    int tid = threadIdx.x;

    float v[4];
    float s = 0.f;
#pragma unroll
    for (int i = 0; i < 4; i++) {
        int c = tid + i * 256;
        v[i] = x[base + c] + a[base + c];
        s += v[i];
    }
    for (int o = 16; o; o >>= 1) s += __shfl_xor_sync(0xffffffffu, s, o);
    if ((tid & 31) == 0) red[tid >> 5] = s;
    __syncthreads();
    if (tid == 0) {
        float t = 0.f;
        for (int w = 0; w < 8; w++) t += red[w];
        red[8] = t * (1.0f / DIM);
    }
    __syncthreads();
    float mean = red[8];

    float vs = 0.f;
#pragma unroll
    for (int i = 0; i < 4; i++) { float d = v[i] - mean; vs += d * d; }
    for (int o = 16; o; o >>= 1) vs += __shfl_xor_sync(0xffffffffu, vs, o);
    __syncthreads();
    if ((tid & 31) == 0) red[tid >> 5] = vs;
    __syncthreads();
    if (tid == 0) {
        float t = 0.f;
        for (int w = 0; w < 8; w++) t += red[w];
        red[8] = t * (1.0f / DIM);
    }
    __syncthreads();
    float inv = rsqrtf(red[8] + 1e-5f);

#pragma unroll
    for (int i = 0; i < 4; i++) {
        int c = tid + i * 256;
        x[base + c] = (v[i] - mean) * inv * g[c] + b[c];
    }
}

// ---------------------------------------------------------------------------
// Host-side orchestration
// ---------------------------------------------------------------------------
struct Planes { uint16_t *wh, *wl, *aqh, *aql, *akh, *akl, *avh, *avl, *ffh, *ffl; };

static inline void conv_a(const float* A, uint16_t* Ah, uint16_t* Al, size_t nelem)
{
    conv_a_kernel<<<(unsigned)(nelem / 1024), 256>>>(A, Ah, Al);
}

static inline void gemm_pk(const uint16_t* Ah, const uint16_t* Al,
                           const float* W, const float* bias, float* C,
                           int M, int N, int K, int relu, const Planes& P)
{
    conv_w_kernel<<<dim3(N / 32, K / 32), 256>>>(W, P.wh, P.wl, K, N);
    tgemm_pk<<<dim3(N / 128, M / 128), 256, TG_SMEM_BYTES>>>(
        Ah, Al, P.wh, P.wl, bias, C, M, N, K, relu);
}

static void attention(const float* Xq, const float* Xkv,
                      const float* W, const float* Bb,
                      const int* tok, int causal,
                      float* q, float* k, float* v, float* t,
                      const Planes& P)
{
    const size_t DD = (size_t)DIM * DIM;

    conv_a(Xq, P.aqh, P.aql, (size_t)MROWS * DIM);
    const uint16_t *kh = P.aqh, *kl = P.aql;
    if (Xkv != Xq) {
        conv_a(Xkv, P.akh, P.akl, (size_t)MROWS * DIM);
        kh = P.akh; kl = P.akl;
    }

    gemm_pk(P.aqh, P.aql, W,          Bb,           q, MROWS, DIM, DIM, 0, P);
    gemm_pk(kh,    kl,    W + DD,     Bb + DIM,     k, MROWS, DIM, DIM, 0, P);
    gemm_pk(kh,    kl,    W + 2 * DD, Bb + 2 * DIM, v, MROWS, DIM, DIM, 0, P);

    conv_a(q, P.aqh, P.aql, (size_t)MROWS * DIM);
    conv_a(k, P.akh, P.akl, (size_t)MROWS * DIM);
    conv_vt_kernel<<<dim3(SEQ / 32, DIM / 32, BATCH), 256>>>(v, P.avh, P.avl);
    flash_kernel<<<dim3(SEQ / 128, BATCH * NH), 256, FL_SMEM>>>(
        P.aqh, P.aql, P.akh, P.akl, P.avh, P.avl, tok, q, causal);

    conv_a(q, P.aqh, P.aql, (size_t)MROWS * DIM);
    gemm_pk(P.aqh, P.aql, W + 3 * DD, Bb + 3 * DIM, t, MROWS, DIM, DIM, 0, P);
}

extern "C" void kernel_launch(void* const* d_in, const int* in_sizes, int n_in,
                              void* d_out, int out_size)
{
    (void)in_sizes; (void)n_in; (void)out_size;

    const int*   src        = (const int*)  d_in[0];
    const int*   trg        = (const int*)  d_in[1];
    const float* src_emb    = (const float*)d_in[2];
    const float* trg_emb    = (const float*)d_in[3];
    const float* enc_attn_w = (const float*)d_in[4];
    const float* enc_attn_b = (const float*)d_in[5];
    const float* enc_ff1_w  = (const float*)d_in[6];
    const float* enc_ff1_b  = (const float*)d_in[7];
    const float* enc_ff2_w  = (const float*)d_in[8];
    const float* enc_ff2_b  = (const float*)d_in[9];
    const float* enc_ln_g   = (const float*)d_in[10];
    const float* enc_ln_b   = (const float*)d_in[11];
    const float* dec_self_w = (const float*)d_in[12];
    const float* dec_self_b = (const float*)d_in[13];
    const float* dec_cross_w= (const float*)d_in[14];
    const float* dec_cross_b= (const float*)d_in[15];
    const float* dec_ff1_w  = (const float*)d_in[16];
    const float* dec_ff1_b  = (const float*)d_in[17];
    const float* dec_ff2_w  = (const float*)d_in[18];
    const float* dec_ff2_b  = (const float*)d_in[19];
    const float* dec_ln_g   = (const float*)d_in[20];
    const float* dec_ln_b   = (const float*)d_in[21];
    const float* out_w      = (const float*)d_in[22];
    const float* out_b      = (const float*)d_in[23];
    float* out = (float*)d_out;

    cudaFuncSetAttribute(tgemm_pk,
                         cudaFuncAttributeMaxDynamicSharedMemorySize, TG_SMEM_BYTES);
    cudaFuncSetAttribute(flash_kernel,
                         cudaFuncAttributeMaxDynamicSharedMemorySize, FL_SMEM);

    float *x, *y, *q, *k, *v, *t, *ff;
    cudaGetSymbolAddress((void**)&x,  g_x);
    cudaGetSymbolAddress((void**)&y,  g_y);
    cudaGetSymbolAddress((void**)&q,  g_q);
    cudaGetSymbolAddress((void**)&k,  g_k);
    cudaGetSymbolAddress((void**)&v,  g_v);
    cudaGetSymbolAddress((void**)&t,  g_t);
    cudaGetSymbolAddress((void**)&ff, g_ff);

    Planes P;
    cudaGetSymbolAddress((void**)&P.wh,  g_wh);
    cudaGetSymbolAddress((void**)&P.wl,  g_wl);
    cudaGetSymbolAddress((void**)&P.aqh, g_aqh);
    cudaGetSymbolAddress((void**)&P.aql, g_aql);
    cudaGetSymbolAddress((void**)&P.akh, g_akh);
    cudaGetSymbolAddress((void**)&P.akl, g_akl);
    cudaGetSymbolAddress((void**)&P.avh, g_avh);
    cudaGetSymbolAddress((void**)&P.avl, g_avl);
    cudaGetSymbolAddress((void**)&P.ffh, g_ffh);
    cudaGetSymbolAddress((void**)&P.ffl, g_ffl);

    const size_t DD = (size_t)DIM * DIM;

    // -------------------- encoder --------------------
    embed_kernel<<<MROWS, 256>>>(src, src_emb, x);
    for (int l = 0; l < NL; l++) {
        attention(x, x, enc_attn_w + (size_t)l * 4 * DD, enc_attn_b + (size_t)l * 4 * DIM,
                  src, /*causal=*/0, q, k, v, t, P);
        add_ln_kernel<<<MROWS, 256>>>(x, t,
            enc_ln_g + (size_t)(l * 2 + 0) * DIM, enc_ln_b + (size_t)(l * 2 + 0) * DIM);

        conv_a(x, P.aqh, P.aql, (size_t)MROWS * DIM);
        gemm_pk(P.aqh, P.aql, enc_ff1_w + (size_t)l * DIM * FFD,
                enc_ff1_b + (size_t)l * FFD, ff, MROWS, FFD, DIM, 1, P);
        conv_a(ff, P.ffh, P.ffl, (size_t)MROWS * FFD);
        gemm_pk(P.ffh, P.ffl, enc_ff2_w + (size_t)l * FFD * DIM,
                enc_ff2_b + (size_t)l * DIM, t, MROWS, DIM, FFD, 0, P);
        add_ln_kernel<<<MROWS, 256>>>(x, t,
            enc_ln_g + (size_t)(l * 2 + 1) * DIM, enc_ln_b + (size_t)(l * 2 + 1) * DIM);
    }

    // -------------------- decoder --------------------
    embed_kernel<<<MROWS, 256>>>(trg, trg_emb, y);
    for (int l = 0; l < NL; l++) {
        attention(y, y, dec_self_w + (size_t)l * 4 * DD, dec_self_b + (size_t)l * 4 * DIM,
                  trg, /*causal=*/1, q, k, v, t, P);
        add_ln_kernel<<<MROWS, 256>>>(y, t,
            dec_ln_g + (size_t)(l * 3 + 0) * DIM, dec_ln_b + (size_t)(l * 3 + 0) * DIM);

        attention(y, x, dec_cross_w + (size_t)l * 4 * DD, dec_cross_b + (size_t)l * 4 * DIM,
                  src, /*causal=*/0, q, k, v, t, P);
        add_ln_kernel<<<MROWS, 256>>>(y, t,
            dec_ln_g + (size_t)(l * 3 + 1) * DIM, dec_ln_b + (size_t)(l * 3 + 1) * DIM);

        conv_a(y, P.aqh, P.aql, (size_t)MROWS * DIM);
        gemm_pk(P.aqh, P.aql, dec_ff1_w + (size_t)l * DIM * FFD,
                dec_ff1_b + (size_t)l * FFD, ff, MROWS, FFD, DIM, 1, P);
        conv_a(ff, P.ffh, P.ffl, (size_t)MROWS * FFD);
        gemm_pk(P.ffh, P.ffl, dec_ff2_w + (size_t)l * FFD * DIM,
                dec_ff2_b + (size_t)l * DIM, t, MROWS, DIM, FFD, 0, P);
        add_ln_kernel<<<MROWS, 256>>>(y, t,
            dec_ln_g + (size_t)(l * 3 + 2) * DIM, dec_ln_b + (size_t)(l * 3 + 2) * DIM);
    }

    // -------------------- output projection --------------------
    conv_a(y, P.aqh, P.aql, (size_t)MROWS * DIM);
    gemm_pk(P.aqh, P.aql, out_w, out_b, out, MROWS, VOCAB, DIM, 0, P);
}

// round 17
// speedup vs baseline: 1.0623x; 1.0623x over previous
#include <cuda_runtime.h>
#include <cstdint>

// ---------------------------------------------------------------------------
// Problem constants
// ---------------------------------------------------------------------------
#define DIM   1024
#define SEQ   1024
#define BATCH 4
#define NH    16
#define HDIM  64
#define FFD   4096
#define NL    6
#define MROWS (BATCH * SEQ)   // 4096
#define VOCAB 32000

// ---------------------------------------------------------------------------
// Scratch (static device globals -- no allocation allowed)
// ---------------------------------------------------------------------------
__device__ float g_x [MROWS * DIM];
__device__ float g_y [MROWS * DIM];
__device__ float g_q [MROWS * DIM];
__device__ float g_k [MROWS * DIM];
__device__ float g_v [MROWS * DIM];
__device__ float g_t [MROWS * DIM];
__device__ float g_ff[MROWS * FFD];

// bf16 hi/lo planes (pre-converted operands)
__device__ uint16_t g_wh [(size_t)VOCAB * DIM];
__device__ uint16_t g_wl [(size_t)VOCAB * DIM];
__device__ uint16_t g_aqh[(size_t)MROWS * DIM];
__device__ uint16_t g_aql[(size_t)MROWS * DIM];
__device__ uint16_t g_akh[(size_t)MROWS * DIM];
__device__ uint16_t g_akl[(size_t)MROWS * DIM];
__device__ uint16_t g_avh[(size_t)MROWS * DIM];   // V transposed per head: [b*DIM+d][seq]
__device__ uint16_t g_avl[(size_t)MROWS * DIM];
__device__ uint16_t g_ffh[(size_t)MROWS * FFD];
__device__ uint16_t g_ffl[(size_t)MROWS * FFD];

// ---------------------------------------------------------------------------
// bf16 split helpers. packbf: e0 in LOW 16 bits (memory-first order).
// ---------------------------------------------------------------------------
__device__ __forceinline__ uint32_t packbf(float e0, float e1) {
    uint32_t r;
    asm("cvt.rn.bf16x2.f32 %0, %1, %2;" : "=r"(r) : "f"(e1), "f"(e0));
    return r;
}
__device__ __forceinline__ float bf_lo(uint32_t p) { return __uint_as_float(p << 16); }
__device__ __forceinline__ float bf_hi(uint32_t p) { return __uint_as_float(p & 0xFFFF0000u); }

__device__ __forceinline__ uint32_t smem_u32(const void* p) {
    uint32_t a;
    asm("{ .reg .u64 t; cvta.to.shared.u64 t, %1; cvt.u32.u64 %0, t; }"
        : "=r"(a) : "l"(p));
    return a;
}

// m16n8k16 row.col bf16 MMA, fp32 accumulate (arch-agnostic, sm_80+)
__device__ __forceinline__ void mma_bf16(float* d, const uint32_t* a, const uint32_t* b) {
    asm volatile(
        "mma.sync.aligned.m16n8k16.row.col.f32.bf16.bf16.f32 "
        "{%0,%1,%2,%3}, {%4,%5,%6,%7}, {%8,%9}, {%0,%1,%2,%3};\n"
        : "+f"(d[0]), "+f"(d[1]), "+f"(d[2]), "+f"(d[3])
        : "r"(a[0]), "r"(a[1]), "r"(a[2]), "r"(a[3]), "r"(b[0]), "r"(b[1]));
}

#define CP_ASYNC16(d, s) \
    asm volatile("cp.async.cg.shared.global [%0], [%1], 16;\n" :: "r"(d), "l"(s))
#define CP_COMMIT() asm volatile("cp.async.commit_group;\n" ::: "memory")
#define CP_WAIT_1() asm volatile("cp.async.wait_group 1;\n" ::: "memory")
#define CP_WAIT_0() asm volatile("cp.async.wait_group 0;\n" ::: "memory")

// ---------------------------------------------------------------------------
// conv_a: elementwise fp32 -> bf16 hi/lo planes (same layout)
// ---------------------------------------------------------------------------
__global__ __launch_bounds__(256)
void conv_a_kernel(const float* __restrict__ A, uint16_t* __restrict__ Ah,
                   uint16_t* __restrict__ Al)
{
    size_t i = (size_t)blockIdx.x * 256 + threadIdx.x;
    float4 a = ((const float4*)A)[i];
    uint32_t h01 = packbf(a.x, a.y);
    uint32_t h23 = packbf(a.z, a.w);
    uint32_t l01 = packbf(a.x - bf_lo(h01), a.y - bf_hi(h01));
    uint32_t l23 = packbf(a.z - bf_lo(h23), a.w - bf_hi(h23));
    ((uint2*)Ah)[i] = make_uint2(h01, h23);
    ((uint2*)Al)[i] = make_uint2(l01, l23);
}

// ---------------------------------------------------------------------------
// conv_w: W[K][N] fp32 -> Wt[N][K] bf16 hi/lo (transpose-convert, 32x32 tiles)
// ---------------------------------------------------------------------------
__global__ __launch_bounds__(256)
void conv_w_kernel(const float* __restrict__ B, uint16_t* __restrict__ Bth,
                   uint16_t* __restrict__ Btl, int K, int N)
{
    __shared__ float t[32][33];
    const int k0 = blockIdx.y << 5, n0 = blockIdx.x << 5;
    const int tid = threadIdx.x;
    const int r = tid >> 5, c = tid & 31;
#pragma unroll
    for (int i = 0; i < 4; i++)
        t[r + i * 8][c] = B[(size_t)(k0 + r + i * 8) * N + n0 + c];
    __syncthreads();
#pragma unroll
    for (int it = 0; it < 2; it++) {
        int idx = tid + it * 256;
        int n = idx >> 4, kp = (idx & 15) << 1;
        float b0 = t[kp][n], b1 = t[kp + 1][n];
        uint32_t h = packbf(b0, b1);
        uint32_t l = packbf(b0 - bf_lo(h), b1 - bf_hi(h));
        *(uint32_t*)&Bth[(size_t)(n0 + n) * K + k0 + kp] = h;
        *(uint32_t*)&Btl[(size_t)(n0 + n) * K + k0 + kp] = l;
    }
}

// ---------------------------------------------------------------------------
// conv_vt: V fp32 [b*SEQ+s][DIM] -> Vt bf16 hi/lo [(b*DIM+d)][SEQ]
// grid = (SEQ/32, DIM/32, BATCH)
// ---------------------------------------------------------------------------
__global__ __launch_bounds__(256)
void conv_vt_kernel(const float* __restrict__ V, uint16_t* __restrict__ Vth,
                    uint16_t* __restrict__ Vtl)
{
    __shared__ float tbuf[32][33];
    const int b = blockIdx.z;
    const int s0 = blockIdx.x << 5, d0 = blockIdx.y << 5;
    const int tid = threadIdx.x;
    const int r = tid >> 5, c = tid & 31;
#pragma unroll
    for (int i = 0; i < 4; i++)
        tbuf[r + i * 8][c] = V[(size_t)(b * SEQ + s0 + r + i * 8) * DIM + d0 + c];
    __syncthreads();
#pragma unroll
    for (int it = 0; it < 2; it++) {
        int idx = tid + it * 256;
        int n = idx >> 4, sp = (idx & 15) << 1;
        float v0 = tbuf[sp][n], v1 = tbuf[sp + 1][n];
        uint32_t hh = packbf(v0, v1);
        uint32_t ll = packbf(v0 - bf_lo(hh), v1 - bf_hi(hh));
        size_t o = (size_t)(b * DIM + d0 + n) * SEQ + s0 + sp;
        *(uint32_t*)&Vth[o] = hh;
        *(uint32_t*)&Vtl[o] = ll;
    }
}

// ---------------------------------------------------------------------------
// Tensor-core GEMM on pre-packed bf16 hi/lo planes.
// K chunks of 64 (unchanged work-per-sync), SINGLE smem stage (73.7 KB)
// -> 2 CTAs/SM; the co-resident CTA's MMAs hide this CTA's loads/syncs.
// 128x128 CTA tile, 8 warps (2m x 4n), warp tile 64x32 (4x4 m16n8k16).
// LDAW=72 -> conflict-free 32-bit fragment loads.
// ---------------------------------------------------------------------------
#define LDAW 72
#define PLANE_B (128 * LDAW * 2)          // 18432 bytes per plane
#define STAGE_B (4 * PLANE_B)             // 73728 bytes (single stage)
#define TG_SMEM_BYTES STAGE_B

__global__ __launch_bounds__(256, 2)
void tgemm_pk(const uint16_t* __restrict__ Ah, const uint16_t* __restrict__ Al,
              const uint16_t* __restrict__ Bth, const uint16_t* __restrict__ Btl,
              const float* __restrict__ bias, float* __restrict__ C,
              int M, int N, int K, int relu)
{
    extern __shared__ __align__(16) char smem[];
    const int tid  = threadIdx.x;
    const int wid  = tid >> 5;
    const int lane = tid & 31;
    const int wm   = wid & 1;
    const int wn   = wid >> 1;
    const int brow = blockIdx.y << 7;
    const int bcol = blockIdx.x << 7;
    const uint32_t sb = smem_u32(smem);

    const char* gp[4];
    gp[0] = (const char*)(Ah  + (size_t)brow * K);
    gp[1] = (const char*)(Al  + (size_t)brow * K);
    gp[2] = (const char*)(Bth + (size_t)bcol * K);
    gp[3] = (const char*)(Btl + (size_t)bcol * K);

    const int row_c = tid >> 3;          // copy row (0..31 per pass)
    const int ch_c  = tid & 7;           // 16B chunk within 128B row

    float acc[4][4][4];
#pragma unroll
    for (int mt = 0; mt < 4; mt++)
#pragma unroll
        for (int nt = 0; nt < 4; nt++)
#pragma unroll
            for (int i = 0; i < 4; i++) acc[mt][nt][i] = 0.f;

    const uint16_t* Ahs = (const uint16_t*)smem;
    const uint16_t* Als = Ahs + 128 * LDAW;
    const uint16_t* Bhs = Als + 128 * LDAW;
    const uint16_t* Bls = Bhs + 128 * LDAW;

    const int NCH = K >> 6;

    for (int c = 0; c < NCH; c++) {
        __syncthreads();                 // all warps done reading previous chunk
        const size_t koff = (size_t)c * 128;   // 64 elems * 2B
#pragma unroll
        for (int p = 0; p < 4; p++) {
            uint32_t sp = sb + p * PLANE_B;
            const char* g = gp[p] + koff;
#pragma unroll
            for (int it = 0; it < 4; it++) {
                int row = row_c + it * 32;
                CP_ASYNC16(sp + row * 144 + ch_c * 16,
                           g + (size_t)row * K * 2 + ch_c * 16);
            }
        }
        CP_COMMIT();
        CP_WAIT_0();
        __syncthreads();                 // all copies visible

        const int ar = wm * 64 + (lane >> 2);
        const int bc = wn * 32 + (lane >> 2);
        const int kf = (lane & 3) << 1;
#pragma unroll
        for (int ks = 0; ks < 4; ks++) {
            const int k0 = ks * 16 + kf;

            uint32_t af[4][4];
#pragma unroll
            for (int mt = 0; mt < 4; mt++) {
                int base = (ar + mt * 16) * LDAW + k0;
                af[mt][0] = *(const uint32_t*)&Ahs[base];
                af[mt][1] = *(const uint32_t*)&Ahs[base + 8 * LDAW];
                af[mt][2] = *(const uint32_t*)&Ahs[base + 8];
                af[mt][3] = *(const uint32_t*)&Ahs[base + 8 * LDAW + 8];
            }
            uint32_t bfh[4][2];
#pragma unroll
            for (int nt = 0; nt < 4; nt++) {
                int base = (bc + nt * 8) * LDAW + k0;
                bfh[nt][0] = *(const uint32_t*)&Bhs[base];
                bfh[nt][1] = *(const uint32_t*)&Bhs[base + 8];
            }
            // hi * hi
#pragma unroll
            for (int mt = 0; mt < 4; mt++)
#pragma unroll
                for (int nt = 0; nt < 4; nt++)
                    mma_bf16(acc[mt][nt], af[mt], bfh[nt]);

            // hi * lo
            uint32_t bfl[4][2];
#pragma unroll
            for (int nt = 0; nt < 4; nt++) {
                int base = (bc + nt * 8) * LDAW + k0;
                bfl[nt][0] = *(const uint32_t*)&Bls[base];
                bfl[nt][1] = *(const uint32_t*)&Bls[base + 8];
            }
#pragma unroll
            for (int mt = 0; mt < 4; mt++)
#pragma unroll
                for (int nt = 0; nt < 4; nt++)
                    mma_bf16(acc[mt][nt], af[mt], bfl[nt]);

            // lo * hi (reuse af registers)
#pragma unroll
            for (int mt = 0; mt < 4; mt++) {
                int base = (ar + mt * 16) * LDAW + k0;
                af[mt][0] = *(const uint32_t*)&Als[base];
                af[mt][1] = *(const uint32_t*)&Als[base + 8 * LDAW];
                af[mt][2] = *(const uint32_t*)&Als[base + 8];
                af[mt][3] = *(const uint32_t*)&Als[base + 8 * LDAW + 8];
            }
#pragma unroll
            for (int mt = 0; mt < 4; mt++)
#pragma unroll
                for (int nt = 0; nt < 4; nt++)
                    mma_bf16(acc[mt][nt], af[mt], bfh[nt]);
        }
    }

    // ---- epilogue: bias (+ReLU), direct global stores ----
    const int rb = brow + wm * 64 + (lane >> 2);
    const int cb = bcol + wn * 32 + ((lane & 3) << 1);
#pragma unroll
    for (int nt = 0; nt < 4; nt++) {
        int col = cb + nt * 8;
        float2 bb = *(const float2*)&bias[col];
#pragma unroll
        for (int mt = 0; mt < 4; mt++) {
            int row = rb + mt * 16;
            float2 r0, r1;
            r0.x = acc[mt][nt][0] + bb.x;
            r0.y = acc[mt][nt][1] + bb.y;
            r1.x = acc[mt][nt][2] + bb.x;
            r1.y = acc[mt][nt][3] + bb.y;
            if (relu) {
                r0.x = fmaxf(r0.x, 0.f); r0.y = fmaxf(r0.y, 0.f);
                r1.x = fmaxf(r1.x, 0.f); r1.y = fmaxf(r1.y, 0.f);
            }
            *(float2*)&C[(size_t)row * N + col]       = r0;
            *(float2*)&C[(size_t)(row + 8) * N + col] = r1;
        }
    }
}

// ---------------------------------------------------------------------------
// Fused flash attention (bf16 split-3 MMA, online softmax). Unchanged (R15).
// ---------------------------------------------------------------------------
#define FL_QB    18432
#define FL_KB    18432
#define FL_VB    17408
#define FL_STG   (2 * FL_KB + 2 * FL_VB)
#define FL_SMEM  (2 * FL_QB + 2 * FL_STG + 256)

__global__ __launch_bounds__(256)
void flash_kernel(const uint16_t* __restrict__ Qh, const uint16_t* __restrict__ Ql,
                  const uint16_t* __restrict__ Kh, const uint16_t* __restrict__ Kl,
                  const uint16_t* __restrict__ Vth, const uint16_t* __restrict__ Vtl,
                  const int* __restrict__ tok, float* __restrict__ Og, int causal)
{
    extern __shared__ __align__(16) char sm[];
    const int tid = threadIdx.x, wid = tid >> 5, lane = tid & 31;
    const int g = lane >> 2, t = lane & 3;
    const int bh = blockIdx.y, b = bh >> 4, h = bh & 15;
    const int q0 = blockIdx.x << 7;
    const uint32_t sb = smem_u32(sm);

    const uint16_t* sqh = (const uint16_t*)sm;
    const uint16_t* sql = sqh + 9216;
    char* kok = sm + 2 * FL_QB + 2 * FL_STG;

    const char* Qh_b = (const char*)(Qh + (size_t)(b * SEQ + q0) * DIM + h * HDIM);
    const char* Ql_b = (const char*)(Ql + (size_t)(b * SEQ + q0) * DIM + h * HDIM);
    const char* Kh_b = (const char*)(Kh + (size_t)(b * SEQ) * DIM + h * HDIM);
    const char* Kl_b = (const char*)(Kl + (size_t)(b * SEQ) * DIM + h * HDIM);
    const char* Vh_b = (const char*)(Vth + ((size_t)b * DIM + h * HDIM) * SEQ);
    const char* Vl_b = (const char*)(Vtl + ((size_t)b * DIM + h * HDIM) * SEQ);

    {
        int row = tid >> 3, ch = tid & 7;
#pragma unroll
        for (int it = 0; it < 4; it++) {
            int r = row + it * 32;
            CP_ASYNC16(sb + r * 144 + ch * 16, Qh_b + (size_t)r * (DIM * 2) + ch * 16);
            CP_ASYNC16(sb + FL_QB + r * 144 + ch * 16, Ql_b + (size_t)r * (DIM * 2) + ch * 16);
        }
    }

    auto issue_kv = [&](int kt) {
        int s = kt & 1;
        uint32_t st = sb + 2 * FL_QB + s * FL_STG;
        int row = tid >> 3, ch = tid & 7;
#pragma unroll
        for (int it = 0; it < 4; it++) {
            int r = row + it * 32;
            size_t go = (size_t)(kt * 128 + r) * (DIM * 2) + ch * 16;
            CP_ASYNC16(st + r * 144 + ch * 16, Kh_b + go);
            CP_ASYNC16(st + FL_KB + r * 144 + ch * 16, Kl_b + go);
        }
        int vrow = tid >> 4, vch = tid & 15;
#pragma unroll
        for (int it = 0; it < 4; it++) {
            int d = vrow + it * 16;
            size_t go = (size_t)d * (SEQ * 2) + (size_t)kt * 256 + vch * 16;
            CP_ASYNC16(st + 2 * FL_KB + d * 272 + vch * 16, Vh_b + go);
            CP_ASYNC16(st + 2 * FL_KB + FL_VB + d * 272 + vch * 16, Vl_b + go);
        }
        if (!causal && tid < 128)
            kok[s * 128 + tid] = (char)(tok[b * SEQ + kt * 128 + tid] != 0);
    };
    issue_kv(0);
    CP_COMMIT();

    const int qrow0 = q0 + wid * 16 + g;
    const int qrow1 = qrow0 + 8;
    int qok0 = 1, qok1 = 1;
    if (causal) {
        qok0 = tok[b * SEQ + qrow0] != 0;
        qok1 = tok[b * SEQ + qrow1] != 0;
    }

    float m0 = -1e30f, m1 = -1e30f, l0 = 0.f, l1 = 0.f;
    float Oa[8][4];
#pragma unroll
    for (int i = 0; i < 8; i++) { Oa[i][0] = Oa[i][1] = Oa[i][2] = Oa[i][3] = 0.f; }

    const int NKT = SEQ / 128;
    const int arow = wid * 16 + g;

    for (int kt = 0; kt < NKT; kt++) {
        if (kt + 1 < NKT) { issue_kv(kt + 1); CP_COMMIT(); CP_WAIT_1(); }
        else               { CP_WAIT_0(); }
        __syncthreads();

        const uint16_t* skh = (const uint16_t*)(sm + 2 * FL_QB + (kt & 1) * FL_STG);
        const uint16_t* skl = skh + 9216;
        const uint16_t* svh = (const uint16_t*)((const char*)skh + 2 * FL_KB);
        const uint16_t* svl = svh + 8704;
        const char* kokc = kok + (kt & 1) * 128;

        float acc[16][4];
#pragma unroll
        for (int nt = 0; nt < 16; nt++)
            acc[nt][0] = acc[nt][1] = acc[nt][2] = acc[nt][3] = 0.f;

#pragma unroll 1
        for (int ks = 0; ks < 4; ks++) {
            const int ab = arow * 72 + ks * 16 + t * 2;
            uint32_t aH[4], aL[4];
            aH[0] = *(const uint32_t*)&sqh[ab];
            aH[1] = *(const uint32_t*)&sqh[ab + 8 * 72];
            aH[2] = *(const uint32_t*)&sqh[ab + 8];
            aH[3] = *(const uint32_t*)&sqh[ab + 8 * 72 + 8];
            aL[0] = *(const uint32_t*)&sql[ab];
            aL[1] = *(const uint32_t*)&sql[ab + 8 * 72];
            aL[2] = *(const uint32_t*)&sql[ab + 8];
            aL[3] = *(const uint32_t*)&sql[ab + 8 * 72 + 8];
#pragma unroll
            for (int nt = 0; nt < 16; nt++) {
                const int bb = (nt * 8 + g) * 72 + ks * 16 + t * 2;
                uint32_t bH[2], bL[2];
                bH[0] = *(const uint32_t*)&skh[bb];
                bH[1] = *(const uint32_t*)&skh[bb + 8];
                bL[0] = *(const uint32_t*)&skl[bb];
                bL[1] = *(const uint32_t*)&skl[bb + 8];
                mma_bf16(acc[nt], aH, bH);
                mma_bf16(acc[nt], aH, bL);
                mma_bf16(acc[nt], aL, bH);
            }
        }

        const int kbase = kt * 128;
#pragma unroll
        for (int nt = 0; nt < 16; nt++) {
            int j0 = nt * 8 + t * 2, j1 = j0 + 1;
            int v00, v01, v10, v11;
            if (causal) {
                int kc0 = kbase + j0, kc1 = kbase + j1;
                v00 = qok0 && (kc0 <= qrow0); v01 = qok0 && (kc1 <= qrow0);
                v10 = qok1 && (kc0 <= qrow1); v11 = qok1 && (kc1 <= qrow1);
            } else {
                int kv0 = kokc[j0], kv1 = kokc[j1];
                v00 = kv0; v01 = kv1; v10 = kv0; v11 = kv1;
            }
            acc[nt][0] = v00 ? acc[nt][0] * 0.125f : -1e9f;
            acc[nt][1] = v01 ? acc[nt][1] * 0.125f : -1e9f;
            acc[nt][2] = v10 ? acc[nt][2] * 0.125f : -1e9f;
            acc[nt][3] = v11 ? acc[nt][3] * 0.125f : -1e9f;
        }

        float mx0 = -1e30f, mx1 = -1e30f;
#pragma unroll
        for (int nt = 0; nt < 16; nt++) {
            mx0 = fmaxf(mx0, fmaxf(acc[nt][0], acc[nt][1]));
            mx1 = fmaxf(mx1, fmaxf(acc[nt][2], acc[nt][3]));
        }
        mx0 = fmaxf(mx0, __shfl_xor_sync(0xffffffffu, mx0, 1));
        mx0 = fmaxf(mx0, __shfl_xor_sync(0xffffffffu, mx0, 2));
        mx1 = fmaxf(mx1, __shfl_xor_sync(0xffffffffu, mx1, 1));
        mx1 = fmaxf(mx1, __shfl_xor_sync(0xffffffffu, mx1, 2));

        float m0n = fmaxf(m0, mx0), m1n = fmaxf(m1, mx1);
        float sc0 = __expf(m0 - m0n), sc1 = __expf(m1 - m1n);
        float s0 = 0.f, s1 = 0.f;
#pragma unroll
        for (int nt = 0; nt < 16; nt++) {
            float p0 = __expf(acc[nt][0] - m0n);
            float p1 = __expf(acc[nt][1] - m0n);
            float p2 = __expf(acc[nt][2] - m1n);
            float p3 = __expf(acc[nt][3] - m1n);
            acc[nt][0] = p0; acc[nt][1] = p1; acc[nt][2] = p2; acc[nt][3] = p3;
            s0 += p0 + p1; s1 += p2 + p3;
        }
        s0 += __shfl_xor_sync(0xffffffffu, s0, 1);
        s0 += __shfl_xor_sync(0xffffffffu, s0, 2);
        s1 += __shfl_xor_sync(0xffffffffu, s1, 1);
        s1 += __shfl_xor_sync(0xffffffffu, s1, 2);
        l0 = l0 * sc0 + s0;
        l1 = l1 * sc1 + s1;
        m0 = m0n; m1 = m1n;
#pragma unroll
        for (int ntd = 0; ntd < 8; ntd++) {
            Oa[ntd][0] *= sc0; Oa[ntd][1] *= sc0;
            Oa[ntd][2] *= sc1; Oa[ntd][3] *= sc1;
        }

#pragma unroll
        for (int ks2 = 0; ks2 < 8; ks2++) {
            uint32_t pH[4], pL[4];
            pH[0] = packbf(acc[2 * ks2][0],     acc[2 * ks2][1]);
            pH[1] = packbf(acc[2 * ks2][2],     acc[2 * ks2][3]);
            pH[2] = packbf(acc[2 * ks2 + 1][0], acc[2 * ks2 + 1][1]);
            pH[3] = packbf(acc[2 * ks2 + 1][2], acc[2 * ks2 + 1][3]);
            pL[0] = packbf(acc[2 * ks2][0] - bf_lo(pH[0]),     acc[2 * ks2][1] - bf_hi(pH[0]));
            pL[1] = packbf(acc[2 * ks2][2] - bf_lo(pH[1]),     acc[2 * ks2][3] - bf_hi(pH[1]));
            pL[2] = packbf(acc[2 * ks2 + 1][0] - bf_lo(pH[2]), acc[2 * ks2 + 1][1] - bf_hi(pH[2]));
            pL[3] = packbf(acc[2 * ks2 + 1][2] - bf_lo(pH[3]), acc[2 * ks2 + 1][3] - bf_hi(pH[3]));
#pragma unroll
            for (int ntd = 0; ntd < 8; ntd++) {
                int vb = (ntd * 8 + g) * 136 + ks2 * 16 + t * 2;
                uint32_t vH[2], vL[2];
                vH[0] = *(const uint32_t*)&svh[vb];
                vH[1] = *(const uint32_t*)&svh[vb + 8];
                vL[0] = *(const uint32_t*)&svl[vb];
                vL[1] = *(const uint32_t*)&svl[vb + 8];
                mma_bf16(Oa[ntd], pH, vH);
                mma_bf16(Oa[ntd], pH, vL);
                mma_bf16(Oa[ntd], pL, vH);
            }
        }
    }

    float i0 = 1.f / l0, i1 = 1.f / l1;
    float* o0 = Og + (size_t)(b * SEQ + qrow0) * DIM + h * HDIM;
    float* o1 = Og + (size_t)(b * SEQ + qrow1) * DIM + h * HDIM;
#pragma unroll
    for (int ntd = 0; ntd < 8; ntd++) {
        int dc = ntd * 8 + t * 2;
        *(float2*)&o0[dc] = make_float2(Oa[ntd][0] * i0, Oa[ntd][1] * i0);
        *(float2*)&o1[dc] = make_float2(Oa[ntd][2] * i1, Oa[ntd][3] * i1);
    }
}

// ---------------------------------------------------------------------------
// Embedding + sinusoidal positional encoding
// ---------------------------------------------------------------------------
__global__ __launch_bounds__(256)
void embed_kernel(const int* __restrict__ tok, const float* __restrict__ emb,
                  float* __restrict__ out)
{
    int bs = blockIdx.x;
    int s  = bs & (SEQ - 1);
    int t  = tok[bs];
    const float* e = emb + (size_t)t * DIM;
    float* o = out + (size_t)bs * DIM;
    const float c = (float)(-9.210340371976184 / 1024.0);
#pragma unroll
    for (int i = 0; i < 4; i++) {
        int d  = threadIdx.x + i * 256;
        int i2 = d & ~1;
        float div = expf((float)i2 * c);
        float ang = (float)s * div;
        float pe  = (d & 1) ? cosf(ang) : sinf(ang);
        o[d] = e[d] + pe;
    }
}

// ---------------------------------------------------------------------------
// x = LayerNorm(x + a) * g + b  (in place on x)
// ---------------------------------------------------------------------------
__global__ __launch_bounds__(256)
void add_ln_kernel(float* __restrict__ x, const float* __restrict__ a,
                   const float* __restrict__ g, const float* __restrict__ b)
{
    __shared__ float red[9];
    size_t base = (size_t)blockIdx.x * DIM;
    int tid = threadIdx.x;

    float v[4];
    float s = 0.f;
#pragma unroll
    for (int i = 0; i < 4; i++) {
        int c = tid + i * 256;
        v[i] = x[base + c] + a[base + c];
        s += v[i];
    }
    for (int o = 16; o; o >>= 1) s += __shfl_xor_sync(0xffffffffu, s, o);
    if ((tid & 31) == 0) red[tid >> 5] = s;
    __syncthreads();
    if (tid == 0) {
        float t = 0.f;
        for (int w = 0; w < 8; w++) t += red[w];
        red[8] = t * (1.0f / DIM);
    }
    __syncthreads();
    float mean = red[8];

    float vs = 0.f;
#pragma unroll
    for (int i = 0; i < 4; i++) { float d = v[i] - mean; vs += d * d; }
    for (int o = 16; o; o >>= 1) vs += __shfl_xor_sync(0xffffffffu, vs, o);
    __syncthreads();
    if ((tid & 31) == 0) red[tid >> 5] = vs;
    __syncthreads();
    if (tid == 0) {
        float t = 0.f;
        for (int w = 0; w < 8; w++) t += red[w];
        red[8] = t * (1.0f / DIM);
    }
    __syncthreads();
    float inv = rsqrtf(red[8] + 1e-5f);

#pragma unroll
    for (int i = 0; i < 4; i++) {
        int c = tid + i * 256;
        x[base + c] = (v[i] - mean) * inv * g[c] + b[c];
    }
}

// ---------------------------------------------------------------------------
// Host-side orchestration
// ---------------------------------------------------------------------------
struct Planes { uint16_t *wh, *wl, *aqh, *aql, *akh, *akl, *avh, *avl, *ffh, *ffl; };

static inline void conv_a(const float* A, uint16_t* Ah, uint16_t* Al, size_t nelem)
{
    conv_a_kernel<<<(unsigned)(nelem / 1024), 256>>>(A, Ah, Al);
}

static inline void gemm_pk(const uint16_t* Ah, const uint16_t* Al,
                           const float* W, const float* bias, float* C,
                           int M, int N, int K, int relu, const Planes& P)
{
    conv_w_kernel<<<dim3(N / 32, K / 32), 256>>>(W, P.wh, P.wl, K, N);
    tgemm_pk<<<dim3(N / 128, M / 128), 256, TG_SMEM_BYTES>>>(
        Ah, Al, P.wh, P.wl, bias, C, M, N, K, relu);
}

static void attention(const float* Xq, const float* Xkv,
                      const float* W, const float* Bb,
                      const int* tok, int causal,
                      float* q, float* k, float* v, float* t,
                      const Planes& P)
{
    const size_t DD = (size_t)DIM * DIM;

    conv_a(Xq, P.aqh, P.aql, (size_t)MROWS * DIM);
    const uint16_t *kh = P.aqh, *kl = P.aql;
    if (Xkv != Xq) {
        conv_a(Xkv, P.akh, P.akl, (size_t)MROWS * DIM);
        kh = P.akh; kl = P.akl;
    }

    gemm_pk(P.aqh, P.aql, W,          Bb,           q, MROWS, DIM, DIM, 0, P);
    gemm_pk(kh,    kl,    W + DD,     Bb + DIM,     k, MROWS, DIM, DIM, 0, P);
    gemm_pk(kh,    kl,    W + 2 * DD, Bb + 2 * DIM, v, MROWS, DIM, DIM, 0, P);

    conv_a(q, P.aqh, P.aql, (size_t)MROWS * DIM);
    conv_a(k, P.akh, P.akl, (size_t)MROWS * DIM);
    conv_vt_kernel<<<dim3(SEQ / 32, DIM / 32, BATCH), 256>>>(v, P.avh, P.avl);
    flash_kernel<<<dim3(SEQ / 128, BATCH * NH), 256, FL_SMEM>>>(
        P.aqh, P.aql, P.akh, P.akl, P.avh, P.avl, tok, q, causal);

    conv_a(q, P.aqh, P.aql, (size_t)MROWS * DIM);
    gemm_pk(P.aqh, P.aql, W + 3 * DD, Bb + 3 * DIM, t, MROWS, DIM, DIM, 0, P);
}

extern "C" void kernel_launch(void* const* d_in, const int* in_sizes, int n_in,
                              void* d_out, int out_size)
{
    (void)in_sizes; (void)n_in; (void)out_size;

    const int*   src        = (const int*)  d_in[0];
    const int*   trg        = (const int*)  d_in[1];
    const float* src_emb    = (const float*)d_in[2];
    const float* trg_emb    = (const float*)d_in[3];
    const float* enc_attn_w = (const float*)d_in[4];
    const float* enc_attn_b = (const float*)d_in[5];
    const float* enc_ff1_w  = (const float*)d_in[6];
    const float* enc_ff1_b  = (const float*)d_in[7];
    const float* enc_ff2_w  = (const float*)d_in[8];
    const float* enc_ff2_b  = (const float*)d_in[9];
    const float* enc_ln_g   = (const float*)d_in[10];
    const float* enc_ln_b   = (const float*)d_in[11];
    const float* dec_self_w = (const float*)d_in[12];
    const float* dec_self_b = (const float*)d_in[13];
    const float* dec_cross_w= (const float*)d_in[14];
    const float* dec_cross_b= (const float*)d_in[15];
    const float* dec_ff1_w  = (const float*)d_in[16];
    const float* dec_ff1_b  = (const float*)d_in[17];
    const float* dec_ff2_w  = (const float*)d_in[18];
    const float* dec_ff2_b  = (const float*)d_in[19];
    const float* dec_ln_g   = (const float*)d_in[20];
    const float* dec_ln_b   = (const float*)d_in[21];
    const float* out_w      = (const float*)d_in[22];
    const float* out_b      = (const float*)d_in[23];
    float* out = (float*)d_out;

    cudaFuncSetAttribute(tgemm_pk,
                         cudaFuncAttributeMaxDynamicSharedMemorySize, TG_SMEM_BYTES);
    cudaFuncSetAttribute(flash_kernel,
                         cudaFuncAttributeMaxDynamicSharedMemorySize, FL_SMEM);

    float *x, *y, *q, *k, *v, *t, *ff;
    cudaGetSymbolAddress((void**)&x,  g_x);
    cudaGetSymbolAddress((void**)&y,  g_y);
    cudaGetSymbolAddress((void**)&q,  g_q);
    cudaGetSymbolAddress((void**)&k,  g_k);
    cudaGetSymbolAddress((void**)&v,  g_v);
    cudaGetSymbolAddress((void**)&t,  g_t);
    cudaGetSymbolAddress((void**)&ff, g_ff);

    Planes P;
    cudaGetSymbolAddress((void**)&P.wh,  g_wh);
    cudaGetSymbolAddress((void**)&P.wl,  g_wl);
    cudaGetSymbolAddress((void**)&P.aqh, g_aqh);
    cudaGetSymbolAddress((void**)&P.aql, g_aql);
    cudaGetSymbolAddress((void**)&P.akh, g_akh);
    cudaGetSymbolAddress((void**)&P.akl, g_akl);
    cudaGetSymbolAddress((void**)&P.avh, g_avh);
    cudaGetSymbolAddress((void**)&P.avl, g_avl);
    cudaGetSymbolAddress((void**)&P.ffh, g_ffh);
    cudaGetSymbolAddress((void**)&P.ffl, g_ffl);

    const size_t DD = (size_t)DIM * DIM;

    // -------------------- encoder --------------------
    embed_kernel<<<MROWS, 256>>>(src, src_emb, x);
    for (int l = 0; l < NL; l++) {
        attention(x, x, enc_attn_w + (size_t)l * 4 * DD, enc_attn_b + (size_t)l * 4 * DIM,
                  src, /*causal=*/0, q, k, v, t, P);
        add_ln_kernel<<<MROWS, 256>>>(x, t,
            enc_ln_g + (size_t)(l * 2 + 0) * DIM, enc_ln_b + (size_t)(l * 2 + 0) * DIM);

        conv_a(x, P.aqh, P.aql, (size_t)MROWS * DIM);
        gemm_pk(P.aqh, P.aql, enc_ff1_w + (size_t)l * DIM * FFD,
                enc_ff1_b + (size_t)l * FFD, ff, MROWS, FFD, DIM, 1, P);
        conv_a(ff, P.ffh, P.ffl, (size_t)MROWS * FFD);
        gemm_pk(P.ffh, P.ffl, enc_ff2_w + (size_t)l * FFD * DIM,
                enc_ff2_b + (size_t)l * DIM, t, MROWS, DIM, FFD, 0, P);
        add_ln_kernel<<<MROWS, 256>>>(x, t,
            enc_ln_g + (size_t)(l * 2 + 1) * DIM, enc_ln_b + (size_t)(l * 2 + 1) * DIM);
    }

    // -------------------- decoder --------------------
    embed_kernel<<<MROWS, 256>>>(trg, trg_emb, y);
    for (int l = 0; l < NL; l++) {
        attention(y, y, dec_self_w + (size_t)l * 4 * DD, dec_self_b + (size_t)l * 4 * DIM,
                  trg, /*causal=*/1, q, k, v, t, P);
        add_ln_kernel<<<MROWS, 256>>>(y, t,
            dec_ln_g + (size_t)(l * 3 + 0) * DIM, dec_ln_b + (size_t)(l * 3 + 0) * DIM);

        attention(y, x, dec_cross_w + (size_t)l * 4 * DD, dec_cross_b + (size_t)l * 4 * DIM,
                  src, /*causal=*/0, q, k, v, t, P);
        add_ln_kernel<<<MROWS, 256>>>(y, t,
            dec_ln_g + (size_t)(l * 3 + 1) * DIM, dec_ln_b + (size_t)(l * 3 + 1) * DIM);

        conv_a(y, P.aqh, P.aql, (size_t)MROWS * DIM);
        gemm_pk(P.aqh, P.aql, dec_ff1_w + (size_t)l * DIM * FFD,
                dec_ff1_b + (size_t)l * FFD, ff, MROWS, FFD, DIM, 1, P);
        conv_a(ff, P.ffh, P.ffl, (size_t)MROWS * FFD);
        gemm_pk(P.ffh, P.ffl, dec_ff2_w + (size_t)l * FFD * DIM,
                dec_ff2_b + (size_t)l * DIM, t, MROWS, DIM, FFD, 0, P);
        add_ln_kernel<<<MROWS, 256>>>(y, t,
            dec_ln_g + (size_t)(l * 3 + 2) * DIM, dec_ln_b + (size_t)(l * 3 + 2) * DIM);
    }

    // -------------------- output projection --------------------
    conv_a(y, P.aqh, P.aql, (size_t)MROWS * DIM);
    gemm_pk(P.aqh, P.aql, out_w, out_b, out, MROWS, VOCAB, DIM, 0, P);
}